// round 4
// baseline (speedup 1.0000x reference)
#include <cuda_runtime.h>
#include <cstdint>

#define Bdim 8
#define Ndim 512
#define Pdim 16
#define Cdim 512
#define HD   64
#define BN   (Bdim*Ndim)
#define BNP  (BN*Pdim)
#define BH   (Bdim*8)
#define EP   (HD*Pdim)

#define OFF_XQ 0ull
#define OFF_XK (OFF_XQ + (size_t)BN*Cdim)
#define OFF_Q  (OFF_XK + (size_t)BN*Cdim)
#define OFF_K  (OFF_Q  + (size_t)BN*Cdim)
#define OFF_V  (OFF_K  + (size_t)BN*Cdim)
#define OFF_VP (OFF_V  + (size_t)BNP*Cdim)
#define OFF_S  (OFF_VP + (size_t)BNP*Cdim)
#define OFF_O2 (OFF_S  + (size_t)BH*Ndim*Ndim)
#define OFF_O  (OFF_O2 + (size_t)BNP*Cdim)
#define SCRATCH_FLOATS (OFF_O + (size_t)BNP*Cdim)

__device__ float g_scratch[SCRATCH_FLOATS];

__device__ __forceinline__ uint32_t f2tf(float f) {
    uint32_t u;
    asm("cvt.rna.tf32.f32 %0, %1;" : "=r"(u) : "f"(f));
    return u;
}
__device__ __forceinline__ float f2tff(float f) { return __uint_as_float(f2tf(f)); }

// ---------------- prep ----------------------------------------------------
__global__ void prep_kernel(const float* __restrict__ x,
                            const float* __restrict__ mask,
                            float* __restrict__ xq, float* __restrict__ xk) {
    int bn = blockIdx.x, c = threadIdx.x;
    const float* xb = x + (size_t)bn * Pdim * Cdim;
    const float* mb = mask + (size_t)bn * Pdim;
    float cnt = 0.f, s = 0.f;
#pragma unroll
    for (int p = 0; p < Pdim; p++) {
        float m = mb[p];
        cnt += m;
        s += m * xb[(size_t)p * Cdim + c];
    }
    xq[(size_t)bn * Cdim + c] = xb[c];
    xk[(size_t)bn * Cdim + c] = s / cnt;
}

// ---------------- tf32 GEMM, 128x256 tile, BK=16, 8 warps of 64x64 --------
// A smem record (16B) idx: rec=(mb*2+ks)*32+4g+(tig^(g&3)^ks); comps=[a0..a3]
// B smem record idx: rec=nb*32+4g+(((g>>1)+tig)&3); comps=[k=tig,tig+4,8+tig,12+tig]
// BT=1: logical B[k][n] = Bm[n*ldb + k] (transposed operand).
template<int BT>
__global__ void __launch_bounds__(256)
tg_kernel(const float* __restrict__ A, int lda, size_t sAb, size_t sAh,
          const float* __restrict__ Bm, int ldb, size_t sBb, size_t sBh,
          float* __restrict__ Cm, int ldc, size_t sCb, size_t sCh,
          int K, float alpha, const float* __restrict__ bias) {
    const int zb = blockIdx.z >> 3, zh = blockIdx.z & 7;
    A  += (size_t)zb * sAb + (size_t)zh * sAh;
    Bm += (size_t)zb * sBb + (size_t)zh * sBh;
    Cm += (size_t)zb * sCb + (size_t)zh * sCh;

    __shared__ float4 smA[2][512];    // 16KB
    __shared__ float4 smB[2][1024];   // 32KB

    const int tid = threadIdx.x;
    const int lane = tid & 31, warp = tid >> 5;
    const int g = lane >> 2, tig = lane & 3;
    const int wmb = (warp >> 2) * 4;   // m-block base (units of 16)
    const int wnb = (warp & 3) * 8;    // n-block base (units of 8)
    const size_t row0 = (size_t)blockIdx.y * 128;
    const int col0 = blockIdx.x * 256;

    float acc[4][8][4];
#pragma unroll
    for (int mi = 0; mi < 4; mi++)
#pragma unroll
        for (int ni = 0; ni < 8; ni++)
#pragma unroll
            for (int r = 0; r < 4; r++) acc[mi][ni][r] = 0.f;

    // ldg assignments
    const int a_m = tid >> 1, a_ks = tid & 1;
    const float* Arow = A + (row0 + a_m) * (size_t)lda + a_ks * 8;
    const float* Bcol = BT ? (Bm + (size_t)(col0 + tid) * ldb)
                           : (Bm + col0 + tid);

    float4 aR0, aR1;
    float bv[16];

#define LDG_AB(k0)                                                          \
    {                                                                       \
        aR0 = *(const float4*)(Arow + (k0));                                \
        aR1 = *(const float4*)(Arow + (k0) + 4);                            \
        if (BT) {                                                           \
            _Pragma("unroll")                                               \
            for (int j = 0; j < 4; j++) {                                   \
                float4 v = *(const float4*)(Bcol + (k0) + 4 * j);           \
                bv[4*j] = v.x; bv[4*j+1] = v.y;                             \
                bv[4*j+2] = v.z; bv[4*j+3] = v.w;                           \
            }                                                               \
        } else {                                                            \
            _Pragma("unroll")                                               \
            for (int j = 0; j < 16; j++)                                    \
                bv[j] = Bcol[(size_t)((k0) + j) * ldb];                     \
        }                                                                   \
    }

#define STS_AB(st)                                                          \
    {                                                                       \
        float* as_ = (float*)smA[st];                                       \
        float av[8] = {aR0.x, aR0.y, aR0.z, aR0.w,                          \
                       aR1.x, aR1.y, aR1.z, aR1.w};                         \
        int mb = a_m >> 4, gA = a_m & 7, hi = (a_m >> 3) & 1;               \
        _Pragma("unroll")                                                   \
        for (int j = 0; j < 8; j++) {                                       \
            int slot = (j & 3) ^ (gA & 3) ^ a_ks;                           \
            int rec = (mb * 2 + a_ks) * 32 + 4 * gA + slot;                 \
            as_[rec * 4 + hi + 2 * (j >> 2)] = f2tff(av[j]);                \
        }                                                                   \
        int nb = tid >> 3, gB = tid & 7;                                    \
        _Pragma("unroll")                                                   \
        for (int tc = 0; tc < 4; tc++) {                                    \
            int slot = ((gB >> 1) + tc) & 3;                                \
            float4 v;                                                       \
            v.x = f2tff(bv[tc]);      v.y = f2tff(bv[tc + 4]);              \
            v.z = f2tff(bv[tc + 8]);  v.w = f2tff(bv[tc + 12]);             \
            smB[st][nb * 32 + 4 * gB + slot] = v;                           \
        }                                                                   \
    }

    LDG_AB(0);
    STS_AB(0);
    __syncthreads();

    const int K16 = K >> 4;
    for (int it = 0; it < K16; it++) {
        const int st = it & 1;
        const float4* as_ = smA[st];
        const float4* bs_ = smB[st];

        uint32_t bf[8][4];
        const int slotB = ((g >> 1) + tig) & 3;
#pragma unroll
        for (int ni = 0; ni < 8; ni++) {
            float4 v = bs_[(wnb + ni) * 32 + 4 * g + slotB];
            bf[ni][0] = __float_as_uint(v.x); bf[ni][1] = __float_as_uint(v.y);
            bf[ni][2] = __float_as_uint(v.z); bf[ni][3] = __float_as_uint(v.w);
        }

        const bool more = (it + 1 < K16);
        if (more) LDG_AB((it + 1) * 16);

#pragma unroll
        for (int ks = 0; ks < 2; ks++) {
            uint32_t af[4][4];
            const int slotA = tig ^ (g & 3) ^ ks;
#pragma unroll
            for (int mi = 0; mi < 4; mi++) {
                float4 v = as_[((wmb + mi) * 2 + ks) * 32 + 4 * g + slotA];
                af[mi][0] = __float_as_uint(v.x); af[mi][1] = __float_as_uint(v.y);
                af[mi][2] = __float_as_uint(v.z); af[mi][3] = __float_as_uint(v.w);
            }
#pragma unroll
            for (int mi = 0; mi < 4; mi++)
#pragma unroll
                for (int ni = 0; ni < 8; ni++) {
                    asm volatile(
                        "mma.sync.aligned.m16n8k8.row.col.f32.tf32.tf32.f32 "
                        "{%0,%1,%2,%3}, {%4,%5,%6,%7}, {%8,%9}, {%0,%1,%2,%3};"
                        : "+f"(acc[mi][ni][0]), "+f"(acc[mi][ni][1]),
                          "+f"(acc[mi][ni][2]), "+f"(acc[mi][ni][3])
                        : "r"(af[mi][0]), "r"(af[mi][1]),
                          "r"(af[mi][2]), "r"(af[mi][3]),
                          "r"(bf[ni][2 * ks]), "r"(bf[ni][2 * ks + 1]));
                }
        }
        if (more) STS_AB(st ^ 1);
        __syncthreads();
    }

#pragma unroll
    for (int mi = 0; mi < 4; mi++) {
        size_t r = row0 + (wmb + mi) * 16 + g;
#pragma unroll
        for (int ni = 0; ni < 8; ni++) {
            int c = col0 + (wnb + ni) * 8 + tig * 2;
            float bx = 0.f, by = 0.f;
            if (bias) { bx = bias[c]; by = bias[c + 1]; }
            *(float2*)&Cm[r * ldc + c] =
                make_float2(acc[mi][ni][0] * alpha + bx, acc[mi][ni][1] * alpha + by);
            *(float2*)&Cm[(r + 8) * ldc + c] =
                make_float2(acc[mi][ni][2] * alpha + bx, acc[mi][ni][3] * alpha + by);
        }
    }
}

// ---------------- softmax (rows of 512) -----------------------------------
__global__ void __launch_bounds__(256)
softmax_kernel(float* __restrict__ S) {
    float* r = S + (size_t)blockIdx.x * Ndim;
    int tid = threadIdx.x;
    float v0 = r[tid], v1 = r[tid + 256];
    __shared__ float red[8];
    unsigned full = 0xffffffffu;
    float m = fmaxf(v0, v1);
#pragma unroll
    for (int o = 16; o; o >>= 1) m = fmaxf(m, __shfl_xor_sync(full, m, o));
    if ((tid & 31) == 0) red[tid >> 5] = m;
    __syncthreads();
    float mm = fmaxf(fmaxf(fmaxf(red[0], red[1]), fmaxf(red[2], red[3])),
                     fmaxf(fmaxf(red[4], red[5]), fmaxf(red[6], red[7])));
    __syncthreads();
    float e0 = __expf(v0 - mm), e1 = __expf(v1 - mm);
    float s = e0 + e1;
#pragma unroll
    for (int o = 16; o; o >>= 1) s += __shfl_xor_sync(full, s, o);
    if ((tid & 31) == 0) red[tid >> 5] = s;
    __syncthreads();
    float inv = 1.0f / (red[0]+red[1]+red[2]+red[3]+red[4]+red[5]+red[6]+red[7]);
    r[tid] = e0 * inv;
    r[tid + 256] = e1 * inv;
}

// ---------------- pack V: Vp[bh, m, d*16+p] = V[b, m, p, h*64+d] ----------
__global__ void __launch_bounds__(256)
packV_kernel(const float* __restrict__ V, float* __restrict__ Vp) {
    int blk = blockIdx.x;
    int m = blk & 511, bh = blk >> 9;
    int b = bh >> 3, h = bh & 7;
    const float* src = V + (size_t)(b * Ndim + m) * Pdim * Cdim + h * HD;
    float* dst = Vp + (size_t)blk * EP;
    __shared__ float tile[Pdim][HD];
    int tid = threadIdx.x;
    int p = tid >> 4, d = (tid & 15) * 4;
    float4 v = *(const float4*)&src[(size_t)p * Cdim + d];
    tile[p][d] = v.x; tile[p][d+1] = v.y; tile[p][d+2] = v.z; tile[p][d+3] = v.w;
    __syncthreads();
    int e0 = tid * 4;
    float4 o;
    o.x = tile[(e0+0) & 15][(e0+0) >> 4];
    o.y = tile[(e0+1) & 15][(e0+1) >> 4];
    o.z = tile[(e0+2) & 15][(e0+2) >> 4];
    o.w = tile[(e0+3) & 15][(e0+3) >> 4];
    *(float4*)&dst[e0] = o;
}

// ---------------- unpack O: O[b,n,p,h*64+d] = O2[bh, n, d*16+p] -----------
__global__ void __launch_bounds__(256)
unpackO_kernel(const float* __restrict__ O2, float* __restrict__ O) {
    int blk = blockIdx.x;
    int n = blk & 511, bh = blk >> 9;
    int b = bh >> 3, h = bh & 7;
    const float* src = O2 + (size_t)blk * EP;
    float* dst = O + (size_t)(b * Ndim + n) * Pdim * Cdim + h * HD;
    __shared__ float tile[EP];
    int tid = threadIdx.x;
    *(float4*)&tile[tid * 4] = *(const float4*)&src[tid * 4];
    __syncthreads();
    int p = tid >> 4, d = (tid & 15) * 4;
    float4 o;
    o.x = tile[(d+0) * 16 + p];
    o.y = tile[(d+1) * 16 + p];
    o.z = tile[(d+2) * 16 + p];
    o.w = tile[(d+3) * 16 + p];
    *(float4*)&dst[(size_t)p * Cdim + d] = o;
}

// ---------------------------------------------------------------------------
extern "C" void kernel_launch(void* const* d_in, const int* in_sizes, int n_in,
                              void* d_out, int out_size) {
    const float* x     = (const float*)d_in[0];
    const float* mask  = (const float*)d_in[1];
    const float* Wqkv  = (const float*)d_in[4];
    const float* Wproj = (const float*)d_in[5];
    const float* bproj = (const float*)d_in[6];
    float* out = (float*)d_out;

    float* sc = nullptr;
    cudaGetSymbolAddress((void**)&sc, g_scratch);
    float* xq = sc + OFF_XQ;
    float* Qb = sc + OFF_Q;
    float* Kb = sc + OFF_K;
    float* Vb = sc + OFF_V;
    float* Vp = sc + OFF_VP;
    float* Sb = sc + OFF_S;
    float* O2 = sc + OFF_O2;
    float* Ob = sc + OFF_O;

    const size_t sNC = (size_t)BN * Cdim;          // 2097152
    const size_t sNN = (size_t)Ndim * Ndim;        // 262144
    const size_t sNE = (size_t)Ndim * EP;          // 524288

    // 1. prep: xq / xk (xk = xq + sNC)
    prep_kernel<<<BN, Cdim>>>(x, mask, xq, sc + OFF_XK);

    // 2. Q and K GEMMs fused over z (A z-stride sNC, B col offset 512, C z-stride sNC)
    tg_kernel<0><<<dim3(2, 32, 2), 256>>>(
        xq, Cdim, 0, sNC, Wqkv, 3 * Cdim, 0, 512, Qb, Cdim, 0, sNC,
        Cdim, 1.f, nullptr);

    // 3. V = x @ Wv
    tg_kernel<0><<<dim3(2, BNP / 128, 1), 256>>>(
        x, Cdim, 0, 0, Wqkv + 2 * Cdim, 3 * Cdim, 0, 0, Vb, Cdim, 0, 0,
        Cdim, 1.f, nullptr);

    // 4. pack V
    packV_kernel<<<BH * Ndim, 256>>>(Vb, Vp);

    // 5. scores: S = (Q Kt^T) * 0.125 via BT mode, K=64
    tg_kernel<1><<<dim3(2, 4, BH), 256>>>(
        Qb, Cdim, sNC / 8 * 8 ? (size_t)Ndim * Cdim : 0, 64,
        Kb, Cdim, (size_t)Ndim * Cdim, 64,
        Sb, Ndim, 8 * sNN, sNN,
        64, 0.125f, nullptr);

    // 6. softmax
    softmax_kernel<<<BH * Ndim, 256>>>(Sb);

    // 7. O2 = S @ Vp  (z batched 64, K=512)
    tg_kernel<0><<<dim3(4, 4, BH), 256>>>(
        Sb, Ndim, 8 * sNN, sNN,
        Vp, EP, 8 * sNE, sNE,
        O2, EP, 8 * sNE, sNE,
        Ndim, 1.f, nullptr);

    // 8. unpack O2
    unpackO_kernel<<<BH * Ndim, 256>>>(O2, Ob);

    // 9. proj
    tg_kernel<0><<<dim3(2, BNP / 128, 1), 256>>>(
        Ob, Cdim, 0, 0, Wproj, Cdim, 0, 0, out, Cdim, 0, 0,
        Cdim, 1.f, bproj);
}